// round 15
// baseline (speedup 1.0000x reference)
#include <cuda_runtime.h>
#include <cuda_fp16.h>

#define NN 100000
#define NE 1600000
#define DIM 32
#define NT 50000
#define NR 64

#define NEP (NE + 3 * NN + 4)   // padded edge capacity (deg rounded up to x4)

#define SCAN_B 512
#define SCAN_NB ((NN + SCAN_B - 1) / SCAN_B)  // 196

#define MM_BLOCKS ((NN + 255) / 256)          // 391
#define CNT_BLOCKS ((NE / 4 + 255) / 256)     // 1563

// ---------------- scratch (static device globals; device-code access only) ----------------
// Invariants across runs: g_deg == 0 on entry (k_scan re-zeroes after consuming);
// g_scan_desc zeroed by k_init each run. Rows NN of g_ah/g_bh are NEVER written ->
// stay zero (.bss) forever; pad edge slots point at them.
__device__ int g_deg[NN];
__device__ int g_rowptr[NN + 1];
__device__ __align__(4) unsigned char g_rank8[NE];   // per-edge rank within its dst row (<256)
__device__ unsigned long long g_scan_desc[SCAN_NB];  // (sum<<32)|flag; 1=agg, 2=prefix
__device__ __align__(16) int g_edge_i[NEP];          // src row index * 8 (uint2 units), padded
__device__ float g_dis[NN];
__device__ __align__(16) __half g_ah[(NN + 1) * DIM];  // fp16: x @ W1^T, then dis-scaled by scan
__device__ __align__(16) __half g_rh[NN * DIM];        // fp16: relu(agg1 + b1)
__device__ __align__(16) __half g_bh[(NN + 1) * DIM];  // fp16: dis .* (g_rh @ W2^T); row NN == 0
__device__ __align__(16) __half g_hh[NN * DIM];        // final node embedding (fp16)

// ---------------- launch 0: tiny init (scan descriptors) ----------------
__global__ void k_init() {
    int i = threadIdx.x;
    if (i < SCAN_NB) g_scan_desc[i] = 0ull;
}

// ---------------- launch 1: fused degree count + rank (uchar) || mm1 (UNscaled) ----------------
__global__ void __launch_bounds__(256) k_count_mm1(const int* __restrict__ dst,
                                                   const float* __restrict__ in,
                                                   const float* __restrict__ W) {
    if (blockIdx.x >= MM_BLOCKS) {
        // ---- count path (4 edges / thread) ----
        int i = (blockIdx.x - MM_BLOCKS) * blockDim.x + threadIdx.x;
        if (i < NE / 4) {
            int4 d4 = reinterpret_cast<const int4*>(dst)[i];
            uchar4 r4;
            r4.x = (unsigned char)atomicAdd(&g_deg[d4.x], 1);
            r4.y = (unsigned char)atomicAdd(&g_deg[d4.y], 1);
            r4.z = (unsigned char)atomicAdd(&g_deg[d4.z], 1);
            r4.w = (unsigned char)atomicAdd(&g_deg[d4.w], 1);
            reinterpret_cast<uchar4*>(g_rank8)[i] = r4;
        }
        return;
    }
    // ---- mm1 path: g_ah[row] = fp16( x[row] @ W1^T )   (dis applied later by k_scan) ----
    __shared__ float sW[DIM * DIM];
    for (int i = threadIdx.x; i < DIM * DIM; i += blockDim.x) sW[i] = W[i];
    __syncthreads();
    int row = blockIdx.x * blockDim.x + threadIdx.x;
    if (row >= NN) return;
    float xv[DIM];
    const float4* xin = reinterpret_cast<const float4*>(in + row * DIM);
    #pragma unroll
    for (int q = 0; q < 8; q++) {
        float4 v = xin[q];
        xv[q * 4 + 0] = v.x; xv[q * 4 + 1] = v.y;
        xv[q * 4 + 2] = v.z; xv[q * 4 + 3] = v.w;
    }
    uint2* o = reinterpret_cast<uint2*>(g_ah + row * DIM);
    #pragma unroll
    for (int jq = 0; jq < 8; jq++) {
        float4 r;
        #pragma unroll
        for (int jj = 0; jj < 4; jj++) {
            int j = jq * 4 + jj;
            float acc = 0.f;
            #pragma unroll
            for (int k = 0; k < DIM; k++) acc = fmaf(xv[k], sW[j * DIM + k], acc);
            (&r.x)[jj] = acc;
        }
        __half2 h0 = __float22half2_rn(make_float2(r.x, r.y));
        __half2 h1 = __float22half2_rn(make_float2(r.z, r.w));
        uint2 u;
        u.x = *reinterpret_cast<unsigned*>(&h0);
        u.y = *reinterpret_cast<unsigned*>(&h1);
        o[jq] = u;
    }
}

__device__ __forceinline__ __half2 u2h(unsigned u) { return *reinterpret_cast<__half2*>(&u); }

// ---------------- launch 2: scan over PADDED degrees + dis + pads + row scaling ----------------
__global__ void __launch_bounds__(SCAN_B) k_scan() {
    __shared__ int s[SCAN_B];
    __shared__ int s_tot;
    __shared__ int s_excl;
    int t = threadIdx.x, b = blockIdx.x;
    int idx = b * SCAN_B + t;
    int v = (idx < NN) ? g_deg[idx] : 0;
    int vp = (v + 3) & ~3;                     // padded degree
    float dd = 0.f;
    if (idx < NN) {
        dd = rsqrtf((float)(v + 1));           // +1 self-loop (real degree)
        g_dis[idx] = dd;
        g_deg[idx] = 0;                        // re-establish invariant for next run
    }
    s[t] = vp;
    __syncthreads();
    #pragma unroll
    for (int off = 1; off < SCAN_B; off <<= 1) {
        int tv = (t >= off) ? s[t - off] : 0;
        __syncthreads();
        s[t] += tv;
        __syncthreads();
    }
    int incl = s[t];
    if (t == SCAN_B - 1) {
        s_tot = incl;
        unsigned long long flag = (b == 0) ? 2ull : 1ull;
        atomicExch(&g_scan_desc[b], ((unsigned long long)(unsigned)incl << 32) | flag);
    }
    // overlap the lookback wait with scaling this thread's feature row by dis
    if (idx < NN) {
        __half2 dh = __float2half2_rn(dd);
        uint4* rowp = reinterpret_cast<uint4*>(g_ah + idx * DIM);
        #pragma unroll
        for (int q = 0; q < 4; q++) {
            uint4 u = rowp[q];
            __half2 h0 = __hmul2(u2h(u.x), dh);
            __half2 h1 = __hmul2(u2h(u.y), dh);
            __half2 h2 = __hmul2(u2h(u.z), dh);
            __half2 h3 = __hmul2(u2h(u.w), dh);
            u.x = *reinterpret_cast<unsigned*>(&h0);
            u.y = *reinterpret_cast<unsigned*>(&h1);
            u.z = *reinterpret_cast<unsigned*>(&h2);
            u.w = *reinterpret_cast<unsigned*>(&h3);
            rowp[q] = u;
        }
    }
    __syncthreads();
    if (t < 32) {
        int excl = 0;
        if (b > 0) {
            int j = b - 1;
            for (;;) {
                int jj = j - t;                      // lane t inspects block jj
                unsigned long long d = 0;
                if (jj >= 0) {
                    do { d = ((volatile unsigned long long*)g_scan_desc)[jj]; }
                    while ((d & 3ull) == 0);
                }
                unsigned fl = (unsigned)(d & 3ull);
                int val = (int)(unsigned)(d >> 32);
                unsigned pmask = __ballot_sync(0xffffffffu, (jj >= 0) && fl == 2u);
                if (pmask) {
                    int L = __ffs(pmask) - 1;        // closest predecessor with full prefix
                    int contrib = (t <= L) ? val : 0;
                    #pragma unroll
                    for (int o = 16; o > 0; o >>= 1) contrib += __shfl_down_sync(~0u, contrib, o);
                    excl += __shfl_sync(~0u, contrib, 0);
                    break;
                } else {
                    int contrib = (jj >= 0) ? val : 0;
                    #pragma unroll
                    for (int o = 16; o > 0; o >>= 1) contrib += __shfl_down_sync(~0u, contrib, o);
                    excl += __shfl_sync(~0u, contrib, 0);
                    j -= 32;
                }
            }
        }
        if (t == 0) {
            s_excl = excl;
            if (b > 0)
                atomicExch(&g_scan_desc[b],
                           ((unsigned long long)(unsigned)(excl + s_tot) << 32) | 2ull);
        }
    }
    __syncthreads();
    if (idx < NN) {
        int r = s_excl + incl - vp;                  // exclusive padded prefix
        g_rowptr[idx] = r;
        for (int j = v; j < vp; j++)                 // pad slots -> zero row NN
            g_edge_i[r + j] = NN * (DIM / 4);
        if (idx == NN - 1) g_rowptr[NN] = r + vp;
    }
}

// ---------------- launch 3 (PROFILED): rank-based CSR fill, no atomics ----------------
__global__ void k_fill(const int* __restrict__ src, const int* __restrict__ dst) {
    int i = blockIdx.x * blockDim.x + threadIdx.x;
    if (i >= NE / 4) return;
    int4 d4 = reinterpret_cast<const int4*>(dst)[i];
    int4 s4 = reinterpret_cast<const int4*>(src)[i];
    uchar4 r4 = reinterpret_cast<const uchar4*>(g_rank8)[i];
    g_edge_i[g_rowptr[d4.x] + r4.x] = s4.x * (DIM / 4);
    g_edge_i[g_rowptr[d4.y] + r4.y] = s4.y * (DIM / 4);
    g_edge_i[g_rowptr[d4.z] + r4.z] = s4.z * (DIM / 4);
    g_edge_i[g_rowptr[d4.w] + r4.w] = s4.w * (DIM / 4);
}

// ---------------- launches 4,6: GCN gather = pure aggregate + relu + fp16 store ----------------
// acc[d] = sum over padded slots of ya[slot]; out = relu(dis_d*(acc + ya[d]) + bias).
// 8-lane group x 4 dims; int4 edge load = 4 edges; 2-level HADD2 tree then fp32 acc.
// PHASE 0: g_ah -> g_rh.   PHASE 1: g_bh -> g_hh.   (W2 applied by k_mm2 between.)
#define GATHER_GRID 888   // 6 blocks/SM x 148, fully resident persistent grid (R13 optimum)
template <int PHASE>
__global__ void __launch_bounds__(256, 6) k_gather(const float* __restrict__ bias) {
    const uint2* __restrict__ xw2 =
        reinterpret_cast<const uint2*>((PHASE == 0) ? g_ah : g_bh);
    uint2* __restrict__ outh =
        reinterpret_cast<uint2*>((PHASE == 0) ? g_rh : g_hh);
    int lane = threadIdx.x & 31;
    int g = lane >> 3;                       // group 0..3 within warp
    int gl = lane & 7;                       // lane within group; owns dims [4gl, 4gl+4)
    const uint2* __restrict__ xwg = xw2 + gl;    // lane-offset base (uint2 = 4 halves)
    const int4* __restrict__ e4 = reinterpret_cast<const int4*>(g_edge_i);
    float4 bias4 = reinterpret_cast<const float4*>(bias)[gl];
    int group = (((blockIdx.x * blockDim.x + threadIdx.x) >> 5) << 2) + g;
    int ngroups = ((gridDim.x * blockDim.x) >> 5) << 2;
    for (int d = group; d < NN; d += ngroups) {
        int p = g_rowptr[d] >> 2;
        int pend = g_rowptr[d + 1] >> 2;     // padded: always whole int4 chunks
        float4 acc = make_float4(0.f, 0.f, 0.f, 0.f);
        for (; p < pend; p++) {
            int4 e = __ldg(&e4[p]);          // 4 edges, group-uniform broadcast
            uint2 u0 = __ldg(&xwg[e.x]);
            uint2 u1 = __ldg(&xwg[e.y]);
            uint2 u2 = __ldg(&xwg[e.z]);
            uint2 u3 = __ldg(&xwg[e.w]);
            __half2 a01 = __hadd2(u2h(u0.x), u2h(u1.x));   // level 1
            __half2 a23 = __hadd2(u2h(u2.x), u2h(u3.x));
            __half2 b01 = __hadd2(u2h(u0.y), u2h(u1.y));
            __half2 b23 = __hadd2(u2h(u2.y), u2h(u3.y));
            __half2 as = __hadd2(a01, a23);                // level 2
            __half2 bs = __hadd2(b01, b23);
            float2 fa = __half22float2(as);
            float2 fb = __half22float2(bs);
            acc.x += fa.x;
            acc.y += fa.y;
            acc.z += fb.x;
            acc.w += fb.y;
        }
        float dd = g_dis[d];
        uint2 us = __ldg(&xwg[d * (DIM / 4)]);     // pre-scaled self row
        float2 s0 = __half22float2(u2h(us.x));
        float2 s1 = __half22float2(u2h(us.y));
        float4 v4;
        v4.x = fmaxf(fmaf(dd, acc.x + s0.x, bias4.x), 0.f);
        v4.y = fmaxf(fmaf(dd, acc.y + s0.y, bias4.y), 0.f);
        v4.z = fmaxf(fmaf(dd, acc.z + s1.x, bias4.z), 0.f);
        v4.w = fmaxf(fmaf(dd, acc.w + s1.y, bias4.w), 0.f);
        __half2 p0 = __float22half2_rn(make_float2(v4.x, v4.y));
        __half2 p1 = __float22half2_rn(make_float2(v4.z, v4.w));
        uint2 up;
        up.x = *reinterpret_cast<unsigned*>(&p0);
        up.y = *reinterpret_cast<unsigned*>(&p1);
        outh[d * (DIM / 4) + gl] = up;
    }
}

// ---------------- launch 5: k_mm2: g_bh = fp16( dis .* (g_rh @ W2^T) ) ----------------
__global__ void __launch_bounds__(256) k_mm2(const float* __restrict__ W) {
    __shared__ float sW[DIM * DIM];
    for (int i = threadIdx.x; i < DIM * DIM; i += blockDim.x) sW[i] = W[i];
    __syncthreads();
    int row = blockIdx.x * blockDim.x + threadIdx.x;
    if (row >= NN) return;
    float dd = g_dis[row];
    float xv[DIM];
    const uint2* rin = reinterpret_cast<const uint2*>(g_rh) + row * (DIM / 4);
    #pragma unroll
    for (int q = 0; q < 8; q++) {
        uint2 u = rin[q];
        float2 f0 = __half22float2(u2h(u.x));
        float2 f1 = __half22float2(u2h(u.y));
        xv[q * 4 + 0] = f0.x; xv[q * 4 + 1] = f0.y;
        xv[q * 4 + 2] = f1.x; xv[q * 4 + 3] = f1.y;
    }
    uint2* o = reinterpret_cast<uint2*>(g_bh) + row * (DIM / 4);
    #pragma unroll
    for (int jq = 0; jq < 8; jq++) {
        float4 r;
        #pragma unroll
        for (int jj = 0; jj < 4; jj++) {
            int j = jq * 4 + jj;
            float acc = 0.f;
            #pragma unroll
            for (int k = 0; k < DIM; k++) acc = fmaf(xv[k], sW[j * DIM + k], acc);
            (&r.x)[jj] = acc * dd;
        }
        __half2 h0 = __float22half2_rn(make_float2(r.x, r.y));
        __half2 h1 = __float22half2_rn(make_float2(r.z, r.w));
        uint2 u;
        u.x = *reinterpret_cast<unsigned*>(&h0);
        u.y = *reinterpret_cast<unsigned*>(&h1);
        o[jq] = u;
    }
}

// ---------------- launch 7: triple embedding + dueling MLP heads, persistent warps ----------------
__device__ __forceinline__ float lay(float x, const float* sw, const float* sb, int lane) {
    float acc = sb[lane];
    #pragma unroll
    for (int k = 0; k < DIM; k++)
        acc = fmaf(__shfl_sync(0xffffffffu, x, k), sw[lane * 33 + k], acc);
    return fmaxf(acc, 0.f);
}

#define TRIPLE_GRID 592
__global__ void __launch_bounds__(256) k_triple(
    const int* __restrict__ head, const int* __restrict__ tail, const int* __restrict__ rel,
    const float* __restrict__ rel_emb,
    const float* __restrict__ aw1, const float* __restrict__ ab1,
    const float* __restrict__ aw2, const float* __restrict__ ab2,
    const float* __restrict__ aw3, const float* __restrict__ ab3,
    const float* __restrict__ vw1, const float* __restrict__ vb1,
    const float* __restrict__ vw2, const float* __restrict__ vb2,
    const float* __restrict__ vw3, const float* __restrict__ vb3,
    float* __restrict__ out) {
    __shared__ float s_aw1[DIM * 33], s_aw2[DIM * 33], s_vw1[DIM * 33], s_vw2[DIM * 33];
    __shared__ float s_aw3[3 * 33], s_vw3[DIM];
    __shared__ float s_ab1[DIM], s_ab2[DIM], s_ab3[3], s_vb1[DIM], s_vb2[DIM];
    __shared__ float s_vb3;
    __shared__ float s_rel[NR * DIM];
    int tid = threadIdx.x;
    for (int i = tid; i < DIM * DIM; i += blockDim.x) {
        int r = i >> 5, c = i & 31;
        s_aw1[r * 33 + c] = aw1[i];
        s_aw2[r * 33 + c] = aw2[i];
        s_vw1[r * 33 + c] = vw1[i];
        s_vw2[r * 33 + c] = vw2[i];
    }
    for (int i = tid; i < 3 * DIM; i += blockDim.x) s_aw3[(i >> 5) * 33 + (i & 31)] = aw3[i];
    for (int i = tid; i < NR * DIM; i += blockDim.x) s_rel[i] = rel_emb[i];
    if (tid < DIM) {
        s_vw3[tid] = vw3[tid];
        s_ab1[tid] = ab1[tid]; s_ab2[tid] = ab2[tid];
        s_vb1[tid] = vb1[tid]; s_vb2[tid] = vb2[tid];
    }
    if (tid < 3) s_ab3[tid] = ab3[tid];
    if (tid == 0) s_vb3 = vb3[0];
    __syncthreads();

    int lane = tid & 31;
    int warp = (blockIdx.x * blockDim.x + tid) >> 5;
    int nwarps = (gridDim.x * blockDim.x) >> 5;
    for (int w = warp; w < NT; w += nwarps) {
        int hd = head[w], tl = tail[w], r = rel[w];
        float xv = __half2float(g_hh[hd * DIM + lane]) + s_rel[r * DIM + lane]
                 + __half2float(g_hh[tl * DIM + lane]);

        float a = lay(xv, s_aw1, s_ab1, lane);
        a = lay(a, s_aw2, s_ab2, lane);
        float v = lay(xv, s_vw1, s_vb1, lane);
        v = lay(v, s_vw2, s_vb2, lane);

        float a3 = (lane < 3) ? s_ab3[lane] : 0.f;
        float vacc = 0.f;
        #pragma unroll
        for (int k = 0; k < DIM; k++) {
            float ha = __shfl_sync(0xffffffffu, a, k);
            float hv = __shfl_sync(0xffffffffu, v, k);
            if (lane < 3) a3 = fmaf(ha, s_aw3[lane * 33 + k], a3);
            vacc = fmaf(hv, s_vw3[k], vacc);
        }
        float val = s_vb3 + vacc;
        float a0 = __shfl_sync(0xffffffffu, a3, 0);
        float a1 = __shfl_sync(0xffffffffu, a3, 1);
        float a2 = __shfl_sync(0xffffffffu, a3, 2);
        float mean = (a0 + a1 + a2) * (1.f / 3.f);
        if (lane < 3) out[w * 3 + lane] = val + a3 - mean;
    }
}

// ---------------- launch: pure kernel launches, only real device pointers ----------------
extern "C" void kernel_launch(void* const* d_in, const int* in_sizes, int n_in,
                              void* d_out, int out_size) {
    (void)in_sizes; (void)n_in; (void)out_size;
    const float* x       = (const float*)d_in[0];
    const int*   ei      = (const int*)d_in[1];
    const int*   head    = (const int*)d_in[2];
    const int*   tail    = (const int*)d_in[3];
    const int*   rel     = (const int*)d_in[4];
    const float* rel_emb = (const float*)d_in[5];
    const float* gw1 = (const float*)d_in[6];
    const float* gb1 = (const float*)d_in[7];
    const float* gw2 = (const float*)d_in[8];
    const float* gb2 = (const float*)d_in[9];
    const float* aw1 = (const float*)d_in[10];
    const float* ab1 = (const float*)d_in[11];
    const float* aw2 = (const float*)d_in[12];
    const float* ab2 = (const float*)d_in[13];
    const float* aw3 = (const float*)d_in[14];
    const float* ab3 = (const float*)d_in[15];
    const float* vw1 = (const float*)d_in[16];
    const float* vb1 = (const float*)d_in[17];
    const float* vw2 = (const float*)d_in[18];
    const float* vb2 = (const float*)d_in[19];
    const float* vw3 = (const float*)d_in[20];
    const float* vb3 = (const float*)d_in[21];
    float* out = (float*)d_out;

    const int* src = ei;
    const int* dst = ei + NE;

    k_init<<<1, 256>>>();                                          // 0: desc reset (tiny)
    k_count_mm1<<<MM_BLOCKS + CNT_BLOCKS, 256>>>(dst, x, gw1);     // 1: count+ranks || mm1
    k_scan<<<SCAN_NB, SCAN_B>>>();                                 // 2: rowptr/dis/pads + row scale
    k_fill<<<(NE / 4 + 255) / 256, 256>>>(src, dst);               // 3: CSR fill (PROFILED)
    k_gather<0><<<GATHER_GRID, 256>>>(gb1);                        // 4: agg1+relu -> g_rh
    k_mm2<<<MM_BLOCKS, 256>>>(gw2);                                // 5: g_bh = dis.*(g_rh @ W2^T)
    k_gather<1><<<GATHER_GRID, 256>>>(gb2);                        // 6: agg2+relu -> g_hh
    k_triple<<<TRIPLE_GRID, 256>>>(head, tail, rel, rel_emb,
                                   aw1, ab1, aw2, ab2, aw3, ab3,
                                   vw1, vb1, vw2, vb2, vw3, vb3, out);  // 7
}

// round 16
// speedup vs baseline: 1.0645x; 1.0645x over previous
#include <cuda_runtime.h>
#include <cuda_fp16.h>

#define NN 100000
#define NE 1600000
#define DIM 32
#define NT 50000
#define NR 64

#define NEP (NE + 3 * NN + 4)   // padded edge capacity (deg rounded up to x4)

#define SCAN_B 512
#define SCAN_NB ((NN + SCAN_B - 1) / SCAN_B)  // 196

#define MM_BLOCKS ((NN + 255) / 256)          // 391
#define FILL_BLOCKS ((NE / 4 + 255) / 256)    // 1563

// ---------------- scratch (static device globals; device-code access only) ----------------
// Invariants across runs: g_deg == 0, g_scan_desc flags == 0 on entry (re-established
// each run). Rows NN of g_ah/g_bh are NEVER written -> stay zero (.bss) forever; pad
// edge slots point at them.
__device__ int g_deg[NN];
__device__ int g_rowptr[NN + 1];
__device__ int g_rank[NE];                           // per-edge rank within its dst row
__device__ unsigned long long g_scan_desc[SCAN_NB];  // (sum<<32)|flag; 1=agg, 2=prefix
__device__ __align__(16) int g_edge_i[NEP];          // src row index * 8 (uint2 units), padded
__device__ float g_dis[NN];
__device__ __align__(16) __half g_ah[(NN + 1) * DIM];  // fp16: dis .* (x @ W1^T); row NN == 0
__device__ __align__(16) __half g_rh[NN * DIM];        // fp16: relu(agg1 + b1)
__device__ __align__(16) __half g_bh[(NN + 1) * DIM];  // fp16: dis .* (g_rh @ W2^T); row NN == 0
__device__ __align__(16) __half g_hh[NN * DIM];        // final node embedding (fp16)

// ---------------- launch 0: degree count + per-edge rank + desc zero ----------------
__global__ void k_count(const int* __restrict__ dst) {
    int i = blockIdx.x * blockDim.x + threadIdx.x;
    if (i < SCAN_NB) g_scan_desc[i] = 0ull;
    if (i >= NE / 4) return;
    int4 d4 = reinterpret_cast<const int4*>(dst)[i];
    int4 r4;
    r4.x = atomicAdd(&g_deg[d4.x], 1);
    r4.y = atomicAdd(&g_deg[d4.y], 1);
    r4.z = atomicAdd(&g_deg[d4.z], 1);
    r4.w = atomicAdd(&g_deg[d4.w], 1);
    reinterpret_cast<int4*>(g_rank)[i] = r4;
}

// ---------------- launch 1: single-pass scan over PADDED degrees + dis + pads ----------------
__global__ void __launch_bounds__(SCAN_B) k_scan() {
    __shared__ int s[SCAN_B];
    __shared__ int s_tot;
    __shared__ int s_excl;
    int t = threadIdx.x, b = blockIdx.x;
    int idx = b * SCAN_B + t;
    int v = (idx < NN) ? g_deg[idx] : 0;
    int vp = (v + 3) & ~3;                     // padded degree
    if (idx < NN) {
        g_dis[idx] = rsqrtf((float)(v + 1));   // +1 self-loop (real degree)
        g_deg[idx] = 0;                        // re-establish invariant for next run
    }
    s[t] = vp;
    __syncthreads();
    #pragma unroll
    for (int off = 1; off < SCAN_B; off <<= 1) {
        int tv = (t >= off) ? s[t - off] : 0;
        __syncthreads();
        s[t] += tv;
        __syncthreads();
    }
    int incl = s[t];
    if (t == SCAN_B - 1) {
        s_tot = incl;
        unsigned long long flag = (b == 0) ? 2ull : 1ull;
        atomicExch(&g_scan_desc[b], ((unsigned long long)(unsigned)incl << 32) | flag);
    }
    __syncthreads();
    if (t < 32) {
        int excl = 0;
        if (b > 0) {
            int j = b - 1;
            for (;;) {
                int jj = j - t;                      // lane t inspects block jj
                unsigned long long d = 0;
                if (jj >= 0) {
                    do { d = ((volatile unsigned long long*)g_scan_desc)[jj]; }
                    while ((d & 3ull) == 0);
                }
                unsigned fl = (unsigned)(d & 3ull);
                int val = (int)(unsigned)(d >> 32);
                unsigned pmask = __ballot_sync(0xffffffffu, (jj >= 0) && fl == 2u);
                if (pmask) {
                    int L = __ffs(pmask) - 1;        // closest predecessor with full prefix
                    int contrib = (t <= L) ? val : 0;
                    #pragma unroll
                    for (int o = 16; o > 0; o >>= 1) contrib += __shfl_down_sync(~0u, contrib, o);
                    excl += __shfl_sync(~0u, contrib, 0);
                    break;
                } else {
                    int contrib = (jj >= 0) ? val : 0;
                    #pragma unroll
                    for (int o = 16; o > 0; o >>= 1) contrib += __shfl_down_sync(~0u, contrib, o);
                    excl += __shfl_sync(~0u, contrib, 0);
                    j -= 32;
                }
            }
        }
        if (t == 0) {
            s_excl = excl;
            if (b > 0)
                atomicExch(&g_scan_desc[b],
                           ((unsigned long long)(unsigned)(excl + s_tot) << 32) | 2ull);
        }
    }
    __syncthreads();
    if (idx < NN) {
        int r = s_excl + incl - vp;                  // exclusive padded prefix
        g_rowptr[idx] = r;
        for (int j = v; j < vp; j++)                 // pad slots -> zero row NN
            g_edge_i[r + j] = NN * (DIM / 4);
        if (idx == NN - 1) g_rowptr[NN] = r + vp;
    }
}

// ---------------- launch 2: fused (mm1 -> fp16 rows) + rank-based CSR fill ----------------
__global__ void __launch_bounds__(256) k_mm_fill(const float* __restrict__ in,
                                                 const float* __restrict__ W,
                                                 const int* __restrict__ src,
                                                 const int* __restrict__ dst) {
    if (blockIdx.x >= MM_BLOCKS) {
        // ---- fill path: pos = rowptr[dst] + rank, no atomics, int4 loads ----
        int i = (blockIdx.x - MM_BLOCKS) * blockDim.x + threadIdx.x;
        if (i < NE / 4) {
            int4 d4 = reinterpret_cast<const int4*>(dst)[i];
            int4 s4 = reinterpret_cast<const int4*>(src)[i];
            int4 r4 = reinterpret_cast<const int4*>(g_rank)[i];
            g_edge_i[g_rowptr[d4.x] + r4.x] = s4.x * (DIM / 4);
            g_edge_i[g_rowptr[d4.y] + r4.y] = s4.y * (DIM / 4);
            g_edge_i[g_rowptr[d4.z] + r4.z] = s4.z * (DIM / 4);
            g_edge_i[g_rowptr[d4.w] + r4.w] = s4.w * (DIM / 4);
        }
        return;
    }
    // ---- mm1 path: g_ah[row] = fp16( dis[row] * (x[row] @ W1^T) ) ----
    __shared__ float sW[DIM * DIM];
    for (int i = threadIdx.x; i < DIM * DIM; i += blockDim.x) sW[i] = W[i];
    __syncthreads();
    int row = blockIdx.x * blockDim.x + threadIdx.x;
    if (row >= NN) return;
    float dd = g_dis[row];
    float xv[DIM];
    const float4* xin = reinterpret_cast<const float4*>(in + row * DIM);
    #pragma unroll
    for (int q = 0; q < 8; q++) {
        float4 v = xin[q];
        xv[q * 4 + 0] = v.x; xv[q * 4 + 1] = v.y;
        xv[q * 4 + 2] = v.z; xv[q * 4 + 3] = v.w;
    }
    uint2* o = reinterpret_cast<uint2*>(g_ah + row * DIM);
    #pragma unroll
    for (int jq = 0; jq < 8; jq++) {
        float4 r;
        #pragma unroll
        for (int jj = 0; jj < 4; jj++) {
            int j = jq * 4 + jj;
            float acc = 0.f;
            #pragma unroll
            for (int k = 0; k < DIM; k++) acc = fmaf(xv[k], sW[j * DIM + k], acc);
            (&r.x)[jj] = acc * dd;
        }
        __half2 h0 = __float22half2_rn(make_float2(r.x, r.y));
        __half2 h1 = __float22half2_rn(make_float2(r.z, r.w));
        uint2 u;
        u.x = *reinterpret_cast<unsigned*>(&h0);
        u.y = *reinterpret_cast<unsigned*>(&h1);
        o[jq] = u;
    }
}

__device__ __forceinline__ __half2 u2h(unsigned u) { return *reinterpret_cast<__half2*>(&u); }

// ---------------- launches 3,5: GCN gather = pure aggregate + relu + fp16 store ----------------
// acc[d] = sum over padded slots of ya[slot]; out = relu(dis_d*(acc + ya[d]) + bias).
// 8-lane group x 4 dims; int4 edge load = 4 edges; 2-level HADD2 tree then fp32 acc.
// PHASE 0: g_ah -> g_rh.   PHASE 1: g_bh -> g_hh.   (W2 applied by k_mm2 between.)
#define GATHER_GRID 888   // 6 blocks/SM x 148, fully resident persistent grid (measured optimum)
template <int PHASE>
__global__ void __launch_bounds__(256, 6) k_gather(const float* __restrict__ bias) {
    const uint2* __restrict__ xw2 =
        reinterpret_cast<const uint2*>((PHASE == 0) ? g_ah : g_bh);
    uint2* __restrict__ outh =
        reinterpret_cast<uint2*>((PHASE == 0) ? g_rh : g_hh);
    int lane = threadIdx.x & 31;
    int g = lane >> 3;                       // group 0..3 within warp
    int gl = lane & 7;                       // lane within group; owns dims [4gl, 4gl+4)
    const uint2* __restrict__ xwg = xw2 + gl;    // lane-offset base (uint2 = 4 halves)
    const int4* __restrict__ e4 = reinterpret_cast<const int4*>(g_edge_i);
    float4 bias4 = reinterpret_cast<const float4*>(bias)[gl];
    int group = (((blockIdx.x * blockDim.x + threadIdx.x) >> 5) << 2) + g;
    int ngroups = ((gridDim.x * blockDim.x) >> 5) << 2;
    for (int d = group; d < NN; d += ngroups) {
        int p = g_rowptr[d] >> 2;
        int pend = g_rowptr[d + 1] >> 2;     // padded: always whole int4 chunks
        float4 acc = make_float4(0.f, 0.f, 0.f, 0.f);
        for (; p < pend; p++) {
            int4 e = __ldg(&e4[p]);          // 4 edges, group-uniform broadcast
            uint2 u0 = __ldg(&xwg[e.x]);
            uint2 u1 = __ldg(&xwg[e.y]);
            uint2 u2 = __ldg(&xwg[e.z]);
            uint2 u3 = __ldg(&xwg[e.w]);
            __half2 a01 = __hadd2(u2h(u0.x), u2h(u1.x));   // level 1
            __half2 a23 = __hadd2(u2h(u2.x), u2h(u3.x));
            __half2 b01 = __hadd2(u2h(u0.y), u2h(u1.y));
            __half2 b23 = __hadd2(u2h(u2.y), u2h(u3.y));
            __half2 as = __hadd2(a01, a23);                // level 2
            __half2 bs = __hadd2(b01, b23);
            float2 fa = __half22float2(as);
            float2 fb = __half22float2(bs);
            acc.x += fa.x;
            acc.y += fa.y;
            acc.z += fb.x;
            acc.w += fb.y;
        }
        float dd = g_dis[d];
        uint2 us = __ldg(&xwg[d * (DIM / 4)]);     // pre-scaled self row
        float2 s0 = __half22float2(u2h(us.x));
        float2 s1 = __half22float2(u2h(us.y));
        float4 v4;
        v4.x = fmaxf(fmaf(dd, acc.x + s0.x, bias4.x), 0.f);
        v4.y = fmaxf(fmaf(dd, acc.y + s0.y, bias4.y), 0.f);
        v4.z = fmaxf(fmaf(dd, acc.z + s1.x, bias4.z), 0.f);
        v4.w = fmaxf(fmaf(dd, acc.w + s1.y, bias4.w), 0.f);
        __half2 p0 = __float22half2_rn(make_float2(v4.x, v4.y));
        __half2 p1 = __float22half2_rn(make_float2(v4.z, v4.w));
        uint2 up;
        up.x = *reinterpret_cast<unsigned*>(&p0);
        up.y = *reinterpret_cast<unsigned*>(&p1);
        outh[d * (DIM / 4) + gl] = up;
    }
}

// ---------------- launch 4: k_mm2: g_bh = fp16( dis .* (g_rh @ W2^T) ) ----------------
__global__ void __launch_bounds__(256) k_mm2(const float* __restrict__ W) {
    __shared__ float sW[DIM * DIM];
    for (int i = threadIdx.x; i < DIM * DIM; i += blockDim.x) sW[i] = W[i];
    __syncthreads();
    int row = blockIdx.x * blockDim.x + threadIdx.x;
    if (row >= NN) return;
    float dd = g_dis[row];
    float xv[DIM];
    const uint2* rin = reinterpret_cast<const uint2*>(g_rh) + row * (DIM / 4);
    #pragma unroll
    for (int q = 0; q < 8; q++) {
        uint2 u = rin[q];
        float2 f0 = __half22float2(u2h(u.x));
        float2 f1 = __half22float2(u2h(u.y));
        xv[q * 4 + 0] = f0.x; xv[q * 4 + 1] = f0.y;
        xv[q * 4 + 2] = f1.x; xv[q * 4 + 3] = f1.y;
    }
    uint2* o = reinterpret_cast<uint2*>(g_bh) + row * (DIM / 4);
    #pragma unroll
    for (int jq = 0; jq < 8; jq++) {
        float4 r;
        #pragma unroll
        for (int jj = 0; jj < 4; jj++) {
            int j = jq * 4 + jj;
            float acc = 0.f;
            #pragma unroll
            for (int k = 0; k < DIM; k++) acc = fmaf(xv[k], sW[j * DIM + k], acc);
            (&r.x)[jj] = acc * dd;
        }
        __half2 h0 = __float22half2_rn(make_float2(r.x, r.y));
        __half2 h1 = __float22half2_rn(make_float2(r.z, r.w));
        uint2 u;
        u.x = *reinterpret_cast<unsigned*>(&h0);
        u.y = *reinterpret_cast<unsigned*>(&h1);
        o[jq] = u;
    }
}

// ---------------- launch 6: triple embedding + dueling MLP heads, persistent warps ----------------
__device__ __forceinline__ float lay(float x, const float* sw, const float* sb, int lane) {
    float acc = sb[lane];
    #pragma unroll
    for (int k = 0; k < DIM; k++)
        acc = fmaf(__shfl_sync(0xffffffffu, x, k), sw[lane * 33 + k], acc);
    return fmaxf(acc, 0.f);
}

#define TRIPLE_GRID 1184   // 8 blocks/SM: more eligible warps for this latency-bound kernel
__global__ void __launch_bounds__(256) k_triple(
    const int* __restrict__ head, const int* __restrict__ tail, const int* __restrict__ rel,
    const float* __restrict__ rel_emb,
    const float* __restrict__ aw1, const float* __restrict__ ab1,
    const float* __restrict__ aw2, const float* __restrict__ ab2,
    const float* __restrict__ aw3, const float* __restrict__ ab3,
    const float* __restrict__ vw1, const float* __restrict__ vb1,
    const float* __restrict__ vw2, const float* __restrict__ vb2,
    const float* __restrict__ vw3, const float* __restrict__ vb3,
    float* __restrict__ out) {
    __shared__ float s_aw1[DIM * 33], s_aw2[DIM * 33], s_vw1[DIM * 33], s_vw2[DIM * 33];
    __shared__ float s_aw3[3 * 33], s_vw3[DIM];
    __shared__ float s_ab1[DIM], s_ab2[DIM], s_ab3[3], s_vb1[DIM], s_vb2[DIM];
    __shared__ float s_vb3;
    __shared__ float s_rel[NR * DIM];
    int tid = threadIdx.x;
    for (int i = tid; i < DIM * DIM; i += blockDim.x) {
        int r = i >> 5, c = i & 31;
        s_aw1[r * 33 + c] = aw1[i];
        s_aw2[r * 33 + c] = aw2[i];
        s_vw1[r * 33 + c] = vw1[i];
        s_vw2[r * 33 + c] = vw2[i];
    }
    for (int i = tid; i < 3 * DIM; i += blockDim.x) s_aw3[(i >> 5) * 33 + (i & 31)] = aw3[i];
    for (int i = tid; i < NR * DIM; i += blockDim.x) s_rel[i] = rel_emb[i];
    if (tid < DIM) {
        s_vw3[tid] = vw3[tid];
        s_ab1[tid] = ab1[tid]; s_ab2[tid] = ab2[tid];
        s_vb1[tid] = vb1[tid]; s_vb2[tid] = vb2[tid];
    }
    if (tid < 3) s_ab3[tid] = ab3[tid];
    if (tid == 0) s_vb3 = vb3[0];
    __syncthreads();

    int lane = tid & 31;
    int warp = (blockIdx.x * blockDim.x + tid) >> 5;
    int nwarps = (gridDim.x * blockDim.x) >> 5;
    const float* wa1 = &s_aw1[lane * 33];
    const float* wv1 = &s_vw1[lane * 33];
    for (int w = warp; w < NT; w += nwarps) {
        int hd = head[w], tl = tail[w], r = rel[w];
        float xv = __half2float(g_hh[hd * DIM + lane]) + s_rel[r * DIM + lane]
                 + __half2float(g_hh[tl * DIM + lane]);

        // fused layer 1 for both heads: one shuffle broadcast serves two FMAs
        float a = s_ab1[lane];
        float v = s_vb1[lane];
        #pragma unroll
        for (int k = 0; k < DIM; k++) {
            float xs = __shfl_sync(0xffffffffu, xv, k);
            a = fmaf(xs, wa1[k], a);
            v = fmaf(xs, wv1[k], v);
        }
        a = fmaxf(a, 0.f);
        v = fmaxf(v, 0.f);

        a = lay(a, s_aw2, s_ab2, lane);
        v = lay(v, s_vw2, s_vb2, lane);

        float a3 = (lane < 3) ? s_ab3[lane] : 0.f;
        float vacc = 0.f;
        #pragma unroll
        for (int k = 0; k < DIM; k++) {
            float ha = __shfl_sync(0xffffffffu, a, k);
            float hv = __shfl_sync(0xffffffffu, v, k);
            if (lane < 3) a3 = fmaf(ha, s_aw3[lane * 33 + k], a3);
            vacc = fmaf(hv, s_vw3[k], vacc);
        }
        float val = s_vb3 + vacc;
        float a0 = __shfl_sync(0xffffffffu, a3, 0);
        float a1 = __shfl_sync(0xffffffffu, a3, 1);
        float a2 = __shfl_sync(0xffffffffu, a3, 2);
        float mean = (a0 + a1 + a2) * (1.f / 3.f);
        if (lane < 3) out[w * 3 + lane] = val + a3 - mean;
    }
}

// ---------------- launch: pure kernel launches, only real device pointers ----------------
extern "C" void kernel_launch(void* const* d_in, const int* in_sizes, int n_in,
                              void* d_out, int out_size) {
    (void)in_sizes; (void)n_in; (void)out_size;
    const float* x       = (const float*)d_in[0];
    const int*   ei      = (const int*)d_in[1];
    const int*   head    = (const int*)d_in[2];
    const int*   tail    = (const int*)d_in[3];
    const int*   rel     = (const int*)d_in[4];
    const float* rel_emb = (const float*)d_in[5];
    const float* gw1 = (const float*)d_in[6];
    const float* gb1 = (const float*)d_in[7];
    const float* gw2 = (const float*)d_in[8];
    const float* gb2 = (const float*)d_in[9];
    const float* aw1 = (const float*)d_in[10];
    const float* ab1 = (const float*)d_in[11];
    const float* aw2 = (const float*)d_in[12];
    const float* ab2 = (const float*)d_in[13];
    const float* aw3 = (const float*)d_in[14];
    const float* ab3 = (const float*)d_in[15];
    const float* vw1 = (const float*)d_in[16];
    const float* vb1 = (const float*)d_in[17];
    const float* vw2 = (const float*)d_in[18];
    const float* vb2 = (const float*)d_in[19];
    const float* vw3 = (const float*)d_in[20];
    const float* vb3 = (const float*)d_in[21];
    float* out = (float*)d_out;

    const int* src = ei;
    const int* dst = ei + NE;

    k_count<<<(NE / 4 + 255) / 256, 256>>>(dst);               // 0: degrees + ranks + desc reset
    k_scan<<<SCAN_NB, SCAN_B>>>();                             // 1: padded rowptr/dis/pads
    k_mm_fill<<<MM_BLOCKS + FILL_BLOCKS, 256>>>(x, gw1, src, dst);  // 2: mm1(fp16) + rank fill
    k_gather<0><<<GATHER_GRID, 256>>>(gb1);                    // 3: agg1+relu -> g_rh (profiled)
    k_mm2<<<MM_BLOCKS, 256>>>(gw2);                            // 4: g_bh = dis.*(g_rh @ W2^T)
    k_gather<1><<<GATHER_GRID, 256>>>(gb2);                    // 5: agg2+relu -> g_hh
    k_triple<<<TRIPLE_GRID, 256>>>(head, tail, rel, rel_emb,
                                   aw1, ab1, aw2, ab2, aw3, ab3,
                                   vw1, vb1, vw2, vb2, vw3, vb3, out);  // 6
}

// round 17
// speedup vs baseline: 1.1836x; 1.1120x over previous
#include <cuda_runtime.h>
#include <cuda_fp16.h>

#define NN 100000
#define NE 1600000
#define DIM 32
#define NT 50000
#define NR 64

#define NEP (NE + 3 * NN + 4)   // padded edge capacity (deg rounded up to x4)

#define SCAN_B 512
#define SCAN_NB ((NN + SCAN_B - 1) / SCAN_B)  // 196

#define MM_BLOCKS ((NN + 255) / 256)          // 391
#define FILL_BLOCKS ((NE / 4 + 255) / 256)    // 1563

// ---------------- scratch (static device globals; device-code access only) ----------------
// Invariants across runs: g_deg == 0, g_scan_desc flags == 0 on entry (re-established
// each run). Rows NN of g_ah/g_bh are NEVER written -> stay zero (.bss) forever; pad
// edge slots point at them.
__device__ int g_deg[NN];
__device__ int g_rowptr[NN + 1];
__device__ __align__(4) unsigned char g_rank8[NE];   // per-edge rank within dst row (<256)
__device__ unsigned long long g_scan_desc[SCAN_NB];  // (sum<<32)|flag; 1=agg, 2=prefix
__device__ __align__(16) int g_edge_i[NEP];          // src row index * 8 (uint2 units), padded
__device__ float g_dis[NN];
__device__ __align__(16) __half g_ah[(NN + 1) * DIM];  // fp16: dis .* (x @ W1^T); row NN == 0
__device__ __align__(16) __half g_rh[NN * DIM];        // fp16: relu(agg1 + b1)
__device__ __align__(16) __half g_bh[(NN + 1) * DIM];  // fp16: dis .* (g_rh @ W2^T); row NN == 0
__device__ __align__(16) __half g_hh[NN * DIM];        // final node embedding (fp16)

// ---------------- launch 0: degree count + per-edge rank (uchar) + desc zero ----------------
__global__ void k_count(const int* __restrict__ dst) {
    int i = blockIdx.x * blockDim.x + threadIdx.x;
    if (i < SCAN_NB) g_scan_desc[i] = 0ull;
    if (i >= NE / 4) return;
    int4 d4 = reinterpret_cast<const int4*>(dst)[i];
    uchar4 r4;
    r4.x = (unsigned char)atomicAdd(&g_deg[d4.x], 1);
    r4.y = (unsigned char)atomicAdd(&g_deg[d4.y], 1);
    r4.z = (unsigned char)atomicAdd(&g_deg[d4.z], 1);
    r4.w = (unsigned char)atomicAdd(&g_deg[d4.w], 1);
    reinterpret_cast<uchar4*>(g_rank8)[i] = r4;
}

// ---------------- launch 1: single-pass scan over PADDED degrees + dis + pads ----------------
__global__ void __launch_bounds__(SCAN_B) k_scan() {
    __shared__ int s[SCAN_B];
    __shared__ int s_tot;
    __shared__ int s_excl;
    int t = threadIdx.x, b = blockIdx.x;
    int idx = b * SCAN_B + t;
    int v = (idx < NN) ? g_deg[idx] : 0;
    int vp = (v + 3) & ~3;                     // padded degree
    if (idx < NN) {
        g_dis[idx] = rsqrtf((float)(v + 1));   // +1 self-loop (real degree)
        g_deg[idx] = 0;                        // re-establish invariant for next run
    }
    s[t] = vp;
    __syncthreads();
    #pragma unroll
    for (int off = 1; off < SCAN_B; off <<= 1) {
        int tv = (t >= off) ? s[t - off] : 0;
        __syncthreads();
        s[t] += tv;
        __syncthreads();
    }
    int incl = s[t];
    if (t == SCAN_B - 1) {
        s_tot = incl;
        unsigned long long flag = (b == 0) ? 2ull : 1ull;
        atomicExch(&g_scan_desc[b], ((unsigned long long)(unsigned)incl << 32) | flag);
    }
    __syncthreads();
    if (t < 32) {
        int excl = 0;
        if (b > 0) {
            int j = b - 1;
            for (;;) {
                int jj = j - t;                      // lane t inspects block jj
                unsigned long long d = 0;
                if (jj >= 0) {
                    do { d = ((volatile unsigned long long*)g_scan_desc)[jj]; }
                    while ((d & 3ull) == 0);
                }
                unsigned fl = (unsigned)(d & 3ull);
                int val = (int)(unsigned)(d >> 32);
                unsigned pmask = __ballot_sync(0xffffffffu, (jj >= 0) && fl == 2u);
                if (pmask) {
                    int L = __ffs(pmask) - 1;        // closest predecessor with full prefix
                    int contrib = (t <= L) ? val : 0;
                    #pragma unroll
                    for (int o = 16; o > 0; o >>= 1) contrib += __shfl_down_sync(~0u, contrib, o);
                    excl += __shfl_sync(~0u, contrib, 0);
                    break;
                } else {
                    int contrib = (jj >= 0) ? val : 0;
                    #pragma unroll
                    for (int o = 16; o > 0; o >>= 1) contrib += __shfl_down_sync(~0u, contrib, o);
                    excl += __shfl_sync(~0u, contrib, 0);
                    j -= 32;
                }
            }
        }
        if (t == 0) {
            s_excl = excl;
            if (b > 0)
                atomicExch(&g_scan_desc[b],
                           ((unsigned long long)(unsigned)(excl + s_tot) << 32) | 2ull);
        }
    }
    __syncthreads();
    if (idx < NN) {
        int r = s_excl + incl - vp;                  // exclusive padded prefix
        g_rowptr[idx] = r;
        for (int j = v; j < vp; j++)                 // pad slots -> zero row NN
            g_edge_i[r + j] = NN * (DIM / 4);
        if (idx == NN - 1) g_rowptr[NN] = r + vp;
    }
}

// ---------------- launch 2: fused (mm1 -> fp16 rows) + rank-based CSR fill ----------------
__global__ void __launch_bounds__(256) k_mm_fill(const float* __restrict__ in,
                                                 const float* __restrict__ W,
                                                 const int* __restrict__ src,
                                                 const int* __restrict__ dst) {
    if (blockIdx.x >= MM_BLOCKS) {
        // ---- fill path: pos = rowptr[dst] + rank, no atomics, vector loads ----
        int i = (blockIdx.x - MM_BLOCKS) * blockDim.x + threadIdx.x;
        if (i < NE / 4) {
            int4 d4 = reinterpret_cast<const int4*>(dst)[i];
            int4 s4 = reinterpret_cast<const int4*>(src)[i];
            uchar4 r4 = reinterpret_cast<const uchar4*>(g_rank8)[i];
            g_edge_i[g_rowptr[d4.x] + r4.x] = s4.x * (DIM / 4);
            g_edge_i[g_rowptr[d4.y] + r4.y] = s4.y * (DIM / 4);
            g_edge_i[g_rowptr[d4.z] + r4.z] = s4.z * (DIM / 4);
            g_edge_i[g_rowptr[d4.w] + r4.w] = s4.w * (DIM / 4);
        }
        return;
    }
    // ---- mm1 path: g_ah[row] = fp16( dis[row] * (x[row] @ W1^T) ) ----
    __shared__ float sW[DIM * DIM];
    for (int i = threadIdx.x; i < DIM * DIM; i += blockDim.x) sW[i] = W[i];
    __syncthreads();
    int row = blockIdx.x * blockDim.x + threadIdx.x;
    if (row >= NN) return;
    float dd = g_dis[row];
    float xv[DIM];
    const float4* xin = reinterpret_cast<const float4*>(in + row * DIM);
    #pragma unroll
    for (int q = 0; q < 8; q++) {
        float4 v = xin[q];
        xv[q * 4 + 0] = v.x; xv[q * 4 + 1] = v.y;
        xv[q * 4 + 2] = v.z; xv[q * 4 + 3] = v.w;
    }
    uint2* o = reinterpret_cast<uint2*>(g_ah + row * DIM);
    #pragma unroll
    for (int jq = 0; jq < 8; jq++) {
        float4 r;
        #pragma unroll
        for (int jj = 0; jj < 4; jj++) {
            int j = jq * 4 + jj;
            float acc = 0.f;
            #pragma unroll
            for (int k = 0; k < DIM; k++) acc = fmaf(xv[k], sW[j * DIM + k], acc);
            (&r.x)[jj] = acc * dd;
        }
        __half2 h0 = __float22half2_rn(make_float2(r.x, r.y));
        __half2 h1 = __float22half2_rn(make_float2(r.z, r.w));
        uint2 u;
        u.x = *reinterpret_cast<unsigned*>(&h0);
        u.y = *reinterpret_cast<unsigned*>(&h1);
        o[jq] = u;
    }
}

__device__ __forceinline__ __half2 u2h(unsigned u) { return *reinterpret_cast<__half2*>(&u); }

// ---------------- launches 3,5: GCN gather = pure aggregate + relu + fp16 store ----------------
// acc[d] = sum over padded slots of ya[slot]; out = relu(dis_d*(acc + ya[d]) + bias).
// 8-lane group x 4 dims; int4 edge load = 4 edges; 2-level HADD2 tree then fp32 acc.
// PHASE 0: g_ah -> g_rh.   PHASE 1: g_bh -> g_hh.   (W2 applied by k_mm2 between.)
#define GATHER_GRID 888   // 6 blocks/SM x 148, fully resident persistent grid (measured optimum)
template <int PHASE>
__global__ void __launch_bounds__(256, 6) k_gather(const float* __restrict__ bias) {
    const uint2* __restrict__ xw2 =
        reinterpret_cast<const uint2*>((PHASE == 0) ? g_ah : g_bh);
    uint2* __restrict__ outh =
        reinterpret_cast<uint2*>((PHASE == 0) ? g_rh : g_hh);
    int lane = threadIdx.x & 31;
    int g = lane >> 3;                       // group 0..3 within warp
    int gl = lane & 7;                       // lane within group; owns dims [4gl, 4gl+4)
    const uint2* __restrict__ xwg = xw2 + gl;    // lane-offset base (uint2 = 4 halves)
    const int4* __restrict__ e4 = reinterpret_cast<const int4*>(g_edge_i);
    float4 bias4 = reinterpret_cast<const float4*>(bias)[gl];
    int group = (((blockIdx.x * blockDim.x + threadIdx.x) >> 5) << 2) + g;
    int ngroups = ((gridDim.x * blockDim.x) >> 5) << 2;
    for (int d = group; d < NN; d += ngroups) {
        int p = g_rowptr[d] >> 2;
        int pend = g_rowptr[d + 1] >> 2;     // padded: always whole int4 chunks
        float4 acc = make_float4(0.f, 0.f, 0.f, 0.f);
        for (; p < pend; p++) {
            int4 e = __ldg(&e4[p]);          // 4 edges, group-uniform broadcast
            uint2 u0 = __ldg(&xwg[e.x]);
            uint2 u1 = __ldg(&xwg[e.y]);
            uint2 u2 = __ldg(&xwg[e.z]);
            uint2 u3 = __ldg(&xwg[e.w]);
            __half2 a01 = __hadd2(u2h(u0.x), u2h(u1.x));   // level 1
            __half2 a23 = __hadd2(u2h(u2.x), u2h(u3.x));
            __half2 b01 = __hadd2(u2h(u0.y), u2h(u1.y));
            __half2 b23 = __hadd2(u2h(u2.y), u2h(u3.y));
            __half2 as = __hadd2(a01, a23);                // level 2
            __half2 bs = __hadd2(b01, b23);
            float2 fa = __half22float2(as);
            float2 fb = __half22float2(bs);
            acc.x += fa.x;
            acc.y += fa.y;
            acc.z += fb.x;
            acc.w += fb.y;
        }
        float dd = g_dis[d];
        uint2 us = __ldg(&xwg[d * (DIM / 4)]);     // pre-scaled self row
        float2 s0 = __half22float2(u2h(us.x));
        float2 s1 = __half22float2(u2h(us.y));
        float4 v4;
        v4.x = fmaxf(fmaf(dd, acc.x + s0.x, bias4.x), 0.f);
        v4.y = fmaxf(fmaf(dd, acc.y + s0.y, bias4.y), 0.f);
        v4.z = fmaxf(fmaf(dd, acc.z + s1.x, bias4.z), 0.f);
        v4.w = fmaxf(fmaf(dd, acc.w + s1.y, bias4.w), 0.f);
        __half2 p0 = __float22half2_rn(make_float2(v4.x, v4.y));
        __half2 p1 = __float22half2_rn(make_float2(v4.z, v4.w));
        uint2 up;
        up.x = *reinterpret_cast<unsigned*>(&p0);
        up.y = *reinterpret_cast<unsigned*>(&p1);
        outh[d * (DIM / 4) + gl] = up;
    }
}

// ---------------- launch 4: k_mm2: g_bh = fp16( dis .* (g_rh @ W2^T) ) ----------------
__global__ void __launch_bounds__(256) k_mm2(const float* __restrict__ W) {
    __shared__ float sW[DIM * DIM];
    for (int i = threadIdx.x; i < DIM * DIM; i += blockDim.x) sW[i] = W[i];
    __syncthreads();
    int row = blockIdx.x * blockDim.x + threadIdx.x;
    if (row >= NN) return;
    float dd = g_dis[row];
    float xv[DIM];
    const uint2* rin = reinterpret_cast<const uint2*>(g_rh) + row * (DIM / 4);
    #pragma unroll
    for (int q = 0; q < 8; q++) {
        uint2 u = rin[q];
        float2 f0 = __half22float2(u2h(u.x));
        float2 f1 = __half22float2(u2h(u.y));
        xv[q * 4 + 0] = f0.x; xv[q * 4 + 1] = f0.y;
        xv[q * 4 + 2] = f1.x; xv[q * 4 + 3] = f1.y;
    }
    uint2* o = reinterpret_cast<uint2*>(g_bh) + row * (DIM / 4);
    #pragma unroll
    for (int jq = 0; jq < 8; jq++) {
        float4 r;
        #pragma unroll
        for (int jj = 0; jj < 4; jj++) {
            int j = jq * 4 + jj;
            float acc = 0.f;
            #pragma unroll
            for (int k = 0; k < DIM; k++) acc = fmaf(xv[k], sW[j * DIM + k], acc);
            (&r.x)[jj] = acc * dd;
        }
        __half2 h0 = __float22half2_rn(make_float2(r.x, r.y));
        __half2 h1 = __float22half2_rn(make_float2(r.z, r.w));
        uint2 u;
        u.x = *reinterpret_cast<unsigned*>(&h0);
        u.y = *reinterpret_cast<unsigned*>(&h1);
        o[jq] = u;
    }
}

// ---------------- launch 6: triple embedding + dueling MLP heads, persistent warps ----------------
__device__ __forceinline__ float lay(float x, const float* sw, const float* sb, int lane) {
    float acc = sb[lane];
    #pragma unroll
    for (int k = 0; k < DIM; k++)
        acc = fmaf(__shfl_sync(0xffffffffu, x, k), sw[lane * 33 + k], acc);
    return fmaxf(acc, 0.f);
}

#define TRIPLE_GRID 1184   // 8 blocks/SM: more eligible warps for this latency-bound kernel
__global__ void __launch_bounds__(256) k_triple(
    const int* __restrict__ head, const int* __restrict__ tail, const int* __restrict__ rel,
    const float* __restrict__ rel_emb,
    const float* __restrict__ aw1, const float* __restrict__ ab1,
    const float* __restrict__ aw2, const float* __restrict__ ab2,
    const float* __restrict__ aw3, const float* __restrict__ ab3,
    const float* __restrict__ vw1, const float* __restrict__ vb1,
    const float* __restrict__ vw2, const float* __restrict__ vb2,
    const float* __restrict__ vw3, const float* __restrict__ vb3,
    float* __restrict__ out) {
    __shared__ float s_aw1[DIM * 33], s_aw2[DIM * 33], s_vw1[DIM * 33], s_vw2[DIM * 33];
    __shared__ float s_aw3[3 * 33], s_vw3[DIM];
    __shared__ float s_ab1[DIM], s_ab2[DIM], s_ab3[3], s_vb1[DIM], s_vb2[DIM];
    __shared__ float s_vb3;
    __shared__ float s_rel[NR * DIM];
    int tid = threadIdx.x;
    for (int i = tid; i < DIM * DIM; i += blockDim.x) {
        int r = i >> 5, c = i & 31;
        s_aw1[r * 33 + c] = aw1[i];
        s_aw2[r * 33 + c] = aw2[i];
        s_vw1[r * 33 + c] = vw1[i];
        s_vw2[r * 33 + c] = vw2[i];
    }
    for (int i = tid; i < 3 * DIM; i += blockDim.x) s_aw3[(i >> 5) * 33 + (i & 31)] = aw3[i];
    for (int i = tid; i < NR * DIM; i += blockDim.x) s_rel[i] = rel_emb[i];
    if (tid < DIM) {
        s_vw3[tid] = vw3[tid];
        s_ab1[tid] = ab1[tid]; s_ab2[tid] = ab2[tid];
        s_vb1[tid] = vb1[tid]; s_vb2[tid] = vb2[tid];
    }
    if (tid < 3) s_ab3[tid] = ab3[tid];
    if (tid == 0) s_vb3 = vb3[0];
    __syncthreads();

    int lane = tid & 31;
    int warp = (blockIdx.x * blockDim.x + tid) >> 5;
    int nwarps = (gridDim.x * blockDim.x) >> 5;
    const float* wa1 = &s_aw1[lane * 33];
    const float* wv1 = &s_vw1[lane * 33];
    // lane-local final-layer weights (per-lane scalars, read once)
    float w3a0 = s_aw3[0 * 33 + lane];
    float w3a1 = s_aw3[1 * 33 + lane];
    float w3a2 = s_aw3[2 * 33 + lane];
    float w3v  = s_vw3[lane];
    for (int w = warp; w < NT; w += nwarps) {
        int hd = head[w], tl = tail[w], r = rel[w];
        float xv = __half2float(g_hh[hd * DIM + lane]) + s_rel[r * DIM + lane]
                 + __half2float(g_hh[tl * DIM + lane]);

        // fused layer 1 for both heads: one shuffle broadcast serves two FMAs
        float a = s_ab1[lane];
        float v = s_vb1[lane];
        #pragma unroll
        for (int k = 0; k < DIM; k++) {
            float xs = __shfl_sync(0xffffffffu, xv, k);
            a = fmaf(xs, wa1[k], a);
            v = fmaf(xs, wv1[k], v);
        }
        a = fmaxf(a, 0.f);
        v = fmaxf(v, 0.f);

        a = lay(a, s_aw2, s_ab2, lane);
        v = lay(v, s_vw2, s_vb2, lane);

        // final layer via 4-value butterfly reduction (all lanes end with full sums)
        float p0 = a * w3a0;
        float p1 = a * w3a1;
        float p2 = a * w3a2;
        float pv = v * w3v;
        #pragma unroll
        for (int off = 16; off > 0; off >>= 1) {
            p0 += __shfl_xor_sync(0xffffffffu, p0, off);
            p1 += __shfl_xor_sync(0xffffffffu, p1, off);
            p2 += __shfl_xor_sync(0xffffffffu, p2, off);
            pv += __shfl_xor_sync(0xffffffffu, pv, off);
        }
        float a0 = p0 + s_ab3[0];
        float a1 = p1 + s_ab3[1];
        float a2 = p2 + s_ab3[2];
        float val = s_vb3 + pv;
        float mean = (a0 + a1 + a2) * (1.f / 3.f);
        if (lane < 3) {
            float aj = (lane == 0) ? a0 : (lane == 1) ? a1 : a2;
            out[w * 3 + lane] = val + aj - mean;
        }
    }
}

// ---------------- launch: pure kernel launches, only real device pointers ----------------
extern "C" void kernel_launch(void* const* d_in, const int* in_sizes, int n_in,
                              void* d_out, int out_size) {
    (void)in_sizes; (void)n_in; (void)out_size;
    const float* x       = (const float*)d_in[0];
    const int*   ei      = (const int*)d_in[1];
    const int*   head    = (const int*)d_in[2];
    const int*   tail    = (const int*)d_in[3];
    const int*   rel     = (const int*)d_in[4];
    const float* rel_emb = (const float*)d_in[5];
    const float* gw1 = (const float*)d_in[6];
    const float* gb1 = (const float*)d_in[7];
    const float* gw2 = (const float*)d_in[8];
    const float* gb2 = (const float*)d_in[9];
    const float* aw1 = (const float*)d_in[10];
    const float* ab1 = (const float*)d_in[11];
    const float* aw2 = (const float*)d_in[12];
    const float* ab2 = (const float*)d_in[13];
    const float* aw3 = (const float*)d_in[14];
    const float* ab3 = (const float*)d_in[15];
    const float* vw1 = (const float*)d_in[16];
    const float* vb1 = (const float*)d_in[17];
    const float* vw2 = (const float*)d_in[18];
    const float* vb2 = (const float*)d_in[19];
    const float* vw3 = (const float*)d_in[20];
    const float* vb3 = (const float*)d_in[21];
    float* out = (float*)d_out;

    const int* src = ei;
    const int* dst = ei + NE;

    k_count<<<(NE / 4 + 255) / 256, 256>>>(dst);               // 0: degrees + ranks + desc reset
    k_scan<<<SCAN_NB, SCAN_B>>>();                             // 1: padded rowptr/dis/pads
    k_mm_fill<<<MM_BLOCKS + FILL_BLOCKS, 256>>>(x, gw1, src, dst);  // 2: mm1(fp16) + rank fill
    k_gather<0><<<GATHER_GRID, 256>>>(gb1);                    // 3: agg1+relu -> g_rh (profiled)
    k_mm2<<<MM_BLOCKS, 256>>>(gw2);                            // 4: g_bh = dis.*(g_rh @ W2^T)
    k_gather<1><<<GATHER_GRID, 256>>>(gb2);                    // 5: agg2+relu -> g_hh
    k_triple<<<TRIPLE_GRID, 256>>>(head, tail, rel, rel_emb,
                                   aw1, ab1, aw2, ab2, aw3, ab3,
                                   vw1, vb1, vw2, vb2, vw3, vb3, out);  // 6
}